// round 9
// baseline (speedup 1.0000x reference)
#include <cuda_runtime.h>
#include <math.h>

#define Nn 8192
#define Dd 512
#define SCAP 1024   // smem candidate list capacity (exact fallback if exceeded)

// ---------------- static device scratch (symbol-access only) ----------------
static __device__ float d_K [(size_t)Nn * Nn];   // log_K on reference fp32 grid
static __device__ float d_KT[(size_t)Nn * Nn];   // transpose (same bits)
static __device__ float d_alpha[Nn];
static __device__ float d_beta [Nn];
static __device__ float d_alpha_prev[Nn];
static __device__ float d_beta_prev [Nn];
static __device__ float d_xsq[Nn];
static __device__ float d_ysq[Nn];
static __device__ int   d_idx[Nn];
static __device__ int   g_done;

// ---- FROZEN NUMERICS (Round 8 pass): XLA-CPU cephes exp, FMA-contracted ----
static __device__ __forceinline__ float exp_fma(float x) {
    x = fminf(x, 88.3762626647950f);
    x = fmaxf(x, -88.3762626647949f);
    float fx = floorf(__fmaf_rn(x, 1.44269504088896341f, 0.5f));
    float r  = __fmaf_rn(fx, -0.693359375f, x);
    r        = __fmaf_rn(fx,  2.12194440e-4f, r);
    float z  = __fmul_rn(r, r);
    float y  = __fmaf_rn(1.9875691500e-4f, r, 1.3981999507e-3f);
    y = __fmaf_rn(y, r, 8.3334519073e-3f);
    y = __fmaf_rn(y, r, 4.1665795894e-2f);
    y = __fmaf_rn(y, r, 1.6666665459e-1f);
    y = __fmaf_rn(y, r, 5.0000001201e-1f);
    y = __fmaf_rn(y, z, r);
    y = __fadd_rn(1.0f, y);
    int n = (int)fx;
    float s = __int_as_float((unsigned)(n + 127) << 23);
    return __fmul_rn(y, s);
}

// ---- FROZEN: XLA-CPU cephes log, FMA-contracted (S >= 1 here) ----
static __device__ __forceinline__ float log_fma(float x) {
    int bits = __float_as_int(x);
    int e = (bits >> 23) - 126;
    float mant = __int_as_float((bits & 0x007fffff) | 0x3f000000);  // [0.5,1)
    if (mant < 0.707106781186547524f) {
        e -= 1;
        mant = __fadd_rn(__fadd_rn(mant, mant), -1.0f);
    } else {
        mant = __fadd_rn(mant, -1.0f);
    }
    float z = __fmul_rn(mant, mant);
    float y = 7.0376836292e-2f;
    y = __fmaf_rn(y, mant, -1.1514610310e-1f);
    y = __fmaf_rn(y, mant,  1.1676998740e-1f);
    y = __fmaf_rn(y, mant, -1.2420140846e-1f);
    y = __fmaf_rn(y, mant,  1.4249322787e-1f);
    y = __fmaf_rn(y, mant, -1.6668057665e-1f);
    y = __fmaf_rn(y, mant,  2.0000714765e-1f);
    y = __fmaf_rn(y, mant, -2.4999993993e-1f);
    y = __fmaf_rn(y, mant,  3.3333331174e-1f);
    y = __fmul_rn(__fmul_rn(y, mant), z);
    float fe = (float)e;
    y = __fmaf_rn(fe, -2.12194440e-4f, y);
    y = __fmaf_rn(-0.5f, z, y);
    float res = __fadd_rn(mant, y);
    res = __fmaf_rn(fe, 0.693359375f, res);
    return res;
}

// FROZEN: XLA vectorized-reduce epilogue, W=8 shuffle-halving combine.
static __device__ __forceinline__ float combine8(const float* s) {
    float w0 = __fadd_rn(s[0], s[4]);
    float w1 = __fadd_rn(s[1], s[5]);
    float w2 = __fadd_rn(s[2], s[6]);
    float w3 = __fadd_rn(s[3], s[7]);
    float u0 = __fadd_rn(w0, w2);
    float u1 = __fadd_rn(w1, w3);
    return __fadd_rn(u0, u1);
}

// ---------------- init ----------------
__global__ void init_kernel() {
    int i = blockIdx.x * blockDim.x + threadIdx.x;
    if (i < Nn) {
        d_beta[i] = 0.0f; d_alpha[i] = 0.0f;
        d_alpha_prev[i] = __int_as_float(0x7fc00000);
        d_beta_prev [i] = __int_as_float(0x7fc00000);
    }
    if (i == 0) g_done = 0;
}

// ---------------- row squared norms: 8-slot FMA chains (FROZEN) -------------
__global__ void rowsq_kernel(const float* __restrict__ X0,
                             const float* __restrict__ X1) {
    int half = (gridDim.x * blockDim.x) >> 1;
    int g = blockIdx.x * blockDim.x + threadIdx.x;
    bool second = g >= half;
    int row = second ? (g - half) : g;
    const float* x = (second ? X1 : X0) + (size_t)row * Dd;
    float s[8];
#pragma unroll
    for (int i = 0; i < 8; i++) s[i] = 0.0f;
    for (int k = 0; k < Dd; k += 8) {
#pragma unroll
        for (int i = 0; i < 8; i++) {
            float v = x[k + i];
            s[i] = __fmaf_rn(v, v, s[i]);
        }
    }
    float r = combine8(s);
    if (second) d_ysq[row] = r; else d_xsq[row] = r;
}

// ---------------- GEMM -> K (FROZEN numerics: sequential-k FMA chain) -------
__global__ void __launch_bounds__(256) gemm_kernel(const float* __restrict__ A,
                                                   const float* __restrict__ B) {
    __shared__ float As[8][128];
    __shared__ float Bs[8][128];
    int bi = blockIdx.y << 7, bj = blockIdx.x << 7;
    int t  = threadIdx.x;
    int tx = t & 15, ty = t >> 4;
    int lrow = t & 127;
    int lk   = (t >> 7) << 2;

    float acc[8][8];
#pragma unroll
    for (int i = 0; i < 8; i++)
#pragma unroll
        for (int j = 0; j < 8; j++) acc[i][j] = 0.f;

    const float* Ag = A + (size_t)(bi + lrow) * Dd + lk;
    const float* Bg = B + (size_t)(bj + lrow) * Dd + lk;

    for (int kt = 0; kt < Dd; kt += 8) {
        float4 av = *(const float4*)(Ag + kt);
        float4 bv = *(const float4*)(Bg + kt);
        __syncthreads();
        As[lk + 0][lrow] = av.x; As[lk + 1][lrow] = av.y;
        As[lk + 2][lrow] = av.z; As[lk + 3][lrow] = av.w;
        Bs[lk + 0][lrow] = bv.x; Bs[lk + 1][lrow] = bv.y;
        Bs[lk + 2][lrow] = bv.z; Bs[lk + 3][lrow] = bv.w;
        __syncthreads();
#pragma unroll
        for (int k = 0; k < 8; k++) {
            float a[8], b[8];
            *(float4*)&a[0] = *(const float4*)&As[k][(ty << 3)];
            *(float4*)&a[4] = *(const float4*)&As[k][(ty << 3) + 4];
            *(float4*)&b[0] = *(const float4*)&Bs[k][(tx << 3)];
            *(float4*)&b[4] = *(const float4*)&Bs[k][(tx << 3) + 4];
#pragma unroll
            for (int i = 0; i < 8; i++)
#pragma unroll
                for (int j = 0; j < 8; j++)
                    acc[i][j] = __fmaf_rn(a[i], b[j], acc[i][j]);
        }
    }

    int row0 = bi + (ty << 3);
    int col0 = bj + (tx << 3);
    float xs[8], ys[8];
#pragma unroll
    for (int i = 0; i < 8; i++) xs[i] = d_xsq[row0 + i];
#pragma unroll
    for (int j = 0; j < 8; j++) ys[j] = d_ysq[col0 + j];
#pragma unroll
    for (int i = 0; i < 8; i++) {
        float o[8];
#pragma unroll
        for (int j = 0; j < 8; j++) {
            float nrm  = __fadd_rn(xs[i], ys[j]);
            float cost = __fmaf_rn(-2.0f, acc[i][j], nrm);
            o[j] = __fdiv_rn(-cost, 0.1f);
        }
        *(float4*)&d_K[(size_t)(row0 + i) * Nn + col0]     = *(float4*)&o[0];
        *(float4*)&d_K[(size_t)(row0 + i) * Nn + col0 + 4] = *(float4*)&o[4];
    }
}

// ---------------- transpose d_K -> d_KT (bitwise copy, one-time) ------------
__global__ void transpose_kernel() {
    __shared__ float tile[32][33];
    int tx = threadIdx.x, ty = threadIdx.y;
    int xi = (blockIdx.x << 5) + tx;
    int yi = (blockIdx.y << 5) + ty;
#pragma unroll
    for (int j = 0; j < 32; j += 8)
        tile[ty + j][tx] = d_K[(size_t)(yi + j) * Nn + xi];
    __syncthreads();
    int xo = (blockIdx.y << 5) + tx;
    int yo = (blockIdx.x << 5) + ty;
#pragma unroll
    for (int j = 0; j < 32; j += 8)
        d_KT[(size_t)(yo + j) * Nn + xo] = tile[tx][ty + j];
}

// =================== FUSED LSE PASS: one global read per row ================
// DIR=0: alpha_i from d_K  + beta  (8-slot vectorized sum order)
// DIR=1: beta_j  from d_KT + alpha (strictly sequential sum order)
// Stages the 32KB row in SMEM: block max -> ordered candidate compaction
// (per-thread chunks + prefix scan => ascending by construction) -> thread-0
// exact ordered sum of candidates (z >= m-70; identical bits to Round 8).
template <int DIR>
__global__ void __launch_bounds__(256) lse_fused_kernel() {
    if (g_done) return;
    __shared__ float z[Nn];           // 32 KB row stage
    __shared__ int   clist[SCAP];     // ascending candidate indices
    __shared__ float wmax[8];
    __shared__ int   offs[257];
    __shared__ float bmax;

    int row = blockIdx.x;
    int t   = threadIdx.x;
    int lane = t & 31, wid = t >> 5;
    const float* __restrict__ Mx  = (DIR == 0) ? d_K  : d_KT;
    const float* __restrict__ vin = (DIR == 0) ? d_beta : d_alpha;
    const float4* src = (const float4*)(Mx + (size_t)row * Nn);
    const float4* vv  = (const float4*)vin;

    // load z = fl(K + v) into smem, track max (max is order-free => exact)
    float lm = __int_as_float(0xff800000);
#pragma unroll
    for (int k = 0; k < 8; k++) {
        int i4 = k * 256 + t;
        float4 a = src[i4];
        float4 b = vv[i4];
        float4 zv;
        zv.x = __fadd_rn(a.x, b.x); zv.y = __fadd_rn(a.y, b.y);
        zv.z = __fadd_rn(a.z, b.z); zv.w = __fadd_rn(a.w, b.w);
        ((float4*)z)[i4] = zv;
        lm = fmaxf(lm, fmaxf(fmaxf(zv.x, zv.y), fmaxf(zv.z, zv.w)));
    }
#pragma unroll
    for (int off = 16; off; off >>= 1)
        lm = fmaxf(lm, __shfl_down_sync(0xffffffffu, lm, off));
    if (lane == 0) wmax[wid] = lm;
    __syncthreads();
    if (t == 0) {
        float m = wmax[0];
#pragma unroll
        for (int w = 1; w < 8; w++) m = fmaxf(m, wmax[w]);
        bmax = m;
    }
    __syncthreads();
    float m   = bmax;
    float thr = m - 70.0f;

    // count candidates in own ascending chunk [t*32, t*32+32)
    int base = t * 32, c = 0;
#pragma unroll 4
    for (int i = 0; i < 32; i++) c += (z[base + i] >= thr);
    offs[t] = c;
    __syncthreads();
    if (t == 0) {                       // serial exclusive scan (256 elems)
        int run = 0;
        for (int i = 0; i < 256; i++) { int v = offs[i]; offs[i] = run; run += v; }
        offs[256] = run;
    }
    __syncthreads();
    int total = offs[256];

    if (total <= SCAP) {
        int o = offs[t];
#pragma unroll 4
        for (int i = 0; i < 32; i++)
            if (z[base + i] >= thr) clist[o++] = base + i;
    }
    __syncthreads();

    if (t == 0) {
        float S;
        if (total <= SCAP) {
            if (DIR == 0) {
                float s[8];
#pragma unroll
                for (int i = 0; i < 8; i++) s[i] = 0.0f;
                for (int p = 0; p < total; p++) {
                    int idx = clist[p];
                    s[idx & 7] = __fadd_rn(s[idx & 7], exp_fma(__fadd_rn(z[idx], -m)));
                }
                S = combine8(s);
            } else {
                float acc = 0.0f;
                for (int p = 0; p < total; p++)
                    acc = __fadd_rn(acc, exp_fma(__fadd_rn(z[clist[p]], -m)));
                S = acc;
            }
        } else {                        // exact fallback: full in-order smem scan
            if (DIR == 0) {
                float s[8];
#pragma unroll
                for (int i = 0; i < 8; i++) s[i] = 0.0f;
                for (int q = 0; q < Nn; q++)
                    if (z[q] >= thr)
                        s[q & 7] = __fadd_rn(s[q & 7], exp_fma(__fadd_rn(z[q], -m)));
                S = combine8(s);
            } else {
                float acc = 0.0f;
                for (int q = 0; q < Nn; q++)
                    if (z[q] >= thr)
                        acc = __fadd_rn(acc, exp_fma(__fadd_rn(z[q], -m)));
                S = acc;
            }
        }
        float res = -__fadd_rn(log_fma(S), m);
        if (DIR == 0) d_alpha[row] = res; else d_beta[row] = res;
    }
}

// ---------------- convergence: exact fp32 fixed point -----------------------
__global__ void __launch_bounds__(1024) conv_kernel() {
    if (g_done) return;
    __shared__ int diff;
    if (threadIdx.x == 0) diff = 0;
    __syncthreads();
    int ld = 0;
    for (int i = threadIdx.x; i < Nn; i += 1024) {
        ld |= (__float_as_int(d_alpha[i]) != __float_as_int(d_alpha_prev[i]));
        ld |= (__float_as_int(d_beta[i])  != __float_as_int(d_beta_prev[i]));
        d_alpha_prev[i] = d_alpha[i];
        d_beta_prev[i]  = d_beta[i];
    }
    if (ld) atomicOr(&diff, 1);
    __syncthreads();
    if (threadIdx.x == 0 && diff == 0) g_done = 1;
}

// ---------------- argmax over P = exp_fma(fl(fl(K+alpha)+beta)) (FROZEN) ----
__global__ void __launch_bounds__(256) argmax_kernel() {
    int rowbase = blockIdx.x << 3;
    int t = threadIdx.x;
    float a[8];
#pragma unroll
    for (int r = 0; r < 8; r++) a[r] = d_alpha[rowbase + r];

    float bv[8]; int bi_[8];
#pragma unroll
    for (int r = 0; r < 8; r++) { bv[r] = -1.0f; bi_[r] = Nn; }

    for (int c = t << 2; c < Nn; c += 1024) {
        float4 betav = *(const float4*)(d_beta + c);
#pragma unroll
        for (int r = 0; r < 8; r++) {
            float4 v = *(const float4*)(d_K + (size_t)(rowbase + r) * Nn + c);
            float w;
            w = exp_fma(__fadd_rn(__fadd_rn(v.x, a[r]), betav.x)); if (w > bv[r]) { bv[r] = w; bi_[r] = c; }
            w = exp_fma(__fadd_rn(__fadd_rn(v.y, a[r]), betav.y)); if (w > bv[r]) { bv[r] = w; bi_[r] = c + 1; }
            w = exp_fma(__fadd_rn(__fadd_rn(v.z, a[r]), betav.z)); if (w > bv[r]) { bv[r] = w; bi_[r] = c + 2; }
            w = exp_fma(__fadd_rn(__fadd_rn(v.w, a[r]), betav.w)); if (w > bv[r]) { bv[r] = w; bi_[r] = c + 3; }
        }
    }
#pragma unroll
    for (int r = 0; r < 8; r++) {
#pragma unroll
        for (int off = 16; off; off >>= 1) {
            float ov = __shfl_down_sync(0xffffffffu, bv[r], off);
            int   oi = __shfl_down_sync(0xffffffffu, bi_[r], off);
            if (ov > bv[r] || (ov == bv[r] && oi < bi_[r])) { bv[r] = ov; bi_[r] = oi; }
        }
    }
    __shared__ float svv[8][8];
    __shared__ int   sii[8][8];
    int wid = t >> 5, lane = t & 31;
    if (lane == 0) {
#pragma unroll
        for (int r = 0; r < 8; r++) { svv[r][wid] = bv[r]; sii[r][wid] = bi_[r]; }
    }
    __syncthreads();
    if (t < 8) {
        float V = -1.0f; int I = Nn;
#pragma unroll
        for (int w = 0; w < 8; w++) {
            float ov = svv[t][w]; int oi = sii[t][w];
            if (ov > V || (ov == V && oi < I)) { V = ov; I = oi; }
        }
        d_idx[rowbase + t] = I;
    }
}

// ---------------- out = concat(x0, x1[idx]) ----------------
__global__ void output_kernel(const float* __restrict__ x0,
                              const float* __restrict__ x1,
                              float* __restrict__ out) {
    int row = blockIdx.x;
    int t   = threadIdx.x;
    const float4* s0 = (const float4*)(x0 + (size_t)row * Dd);
    ((float4*)(out + (size_t)row * Dd))[t] = s0[t];
    int j = d_idx[row];
    const float4* s1 = (const float4*)(x1 + (size_t)j * Dd);
    ((float4*)(out + (size_t)Nn * Dd + (size_t)row * Dd))[t] = s1[t];
}

// ---------------- launch ----------------
extern "C" void kernel_launch(void* const* d_in, const int* in_sizes, int n_in,
                              void* d_out, int out_size) {
    const float* x0 = (const float*)d_in[0];
    const float* x1 = (const float*)d_in[1];
    float* out = (float*)d_out;

    init_kernel<<<8, 1024>>>();
    rowsq_kernel<<<2 * (Nn / 256), 256>>>(x0, x1);

    dim3 gg(Nn / 128, Nn / 128);
    gemm_kernel<<<gg, 256>>>(x0, x1);

    dim3 tg(Nn / 32, Nn / 32), tb(32, 8);
    transpose_kernel<<<tg, tb>>>();

    for (int it = 0; it < 100; it++) {
        lse_fused_kernel<0><<<Nn, 256>>>();
        lse_fused_kernel<1><<<Nn, 256>>>();
        conv_kernel<<<1, 1024>>>();
    }

    argmax_kernel<<<Nn / 8, 256>>>();
    output_kernel<<<Nn, 128>>>(x0, x1, out);
}

// round 10
// speedup vs baseline: 2.4537x; 2.4537x over previous
#include <cuda_runtime.h>
#include <math.h>

#define Nn 8192
#define Dd 512

// ---------------- static device scratch (symbol-access only) ----------------
static __device__ float d_K [(size_t)Nn * Nn];   // log_K on reference fp32 grid
static __device__ float d_KT[(size_t)Nn * Nn];   // transpose (same bits)
static __device__ float d_alpha[Nn];
static __device__ float d_beta [Nn];
static __device__ float d_alpha_prev[Nn];
static __device__ float d_beta_prev [Nn];
static __device__ float d_xsq[Nn];
static __device__ float d_ysq[Nn];
static __device__ int   d_idx[Nn];
static __device__ int   g_done;

// ---- FROZEN NUMERICS (Round 8 pass): XLA-CPU cephes exp, FMA-contracted ----
static __device__ __forceinline__ float exp_fma(float x) {
    x = fminf(x, 88.3762626647950f);
    x = fmaxf(x, -88.3762626647949f);
    float fx = floorf(__fmaf_rn(x, 1.44269504088896341f, 0.5f));
    float r  = __fmaf_rn(fx, -0.693359375f, x);
    r        = __fmaf_rn(fx,  2.12194440e-4f, r);
    float z  = __fmul_rn(r, r);
    float y  = __fmaf_rn(1.9875691500e-4f, r, 1.3981999507e-3f);
    y = __fmaf_rn(y, r, 8.3334519073e-3f);
    y = __fmaf_rn(y, r, 4.1665795894e-2f);
    y = __fmaf_rn(y, r, 1.6666665459e-1f);
    y = __fmaf_rn(y, r, 5.0000001201e-1f);
    y = __fmaf_rn(y, z, r);
    y = __fadd_rn(1.0f, y);
    int n = (int)fx;
    float s = __int_as_float((unsigned)(n + 127) << 23);
    return __fmul_rn(y, s);
}

// ---- FROZEN: XLA-CPU cephes log, FMA-contracted (S >= 1 here) ----
static __device__ __forceinline__ float log_fma(float x) {
    int bits = __float_as_int(x);
    int e = (bits >> 23) - 126;
    float mant = __int_as_float((bits & 0x007fffff) | 0x3f000000);  // [0.5,1)
    if (mant < 0.707106781186547524f) {
        e -= 1;
        mant = __fadd_rn(__fadd_rn(mant, mant), -1.0f);
    } else {
        mant = __fadd_rn(mant, -1.0f);
    }
    float z = __fmul_rn(mant, mant);
    float y = 7.0376836292e-2f;
    y = __fmaf_rn(y, mant, -1.1514610310e-1f);
    y = __fmaf_rn(y, mant,  1.1676998740e-1f);
    y = __fmaf_rn(y, mant, -1.2420140846e-1f);
    y = __fmaf_rn(y, mant,  1.4249322787e-1f);
    y = __fmaf_rn(y, mant, -1.6668057665e-1f);
    y = __fmaf_rn(y, mant,  2.0000714765e-1f);
    y = __fmaf_rn(y, mant, -2.4999993993e-1f);
    y = __fmaf_rn(y, mant,  3.3333331174e-1f);
    y = __fmul_rn(__fmul_rn(y, mant), z);
    float fe = (float)e;
    y = __fmaf_rn(fe, -2.12194440e-4f, y);
    y = __fmaf_rn(-0.5f, z, y);
    float res = __fadd_rn(mant, y);
    res = __fmaf_rn(fe, 0.693359375f, res);
    return res;
}

// ---------------- init ----------------
__global__ void init_kernel() {
    int i = blockIdx.x * blockDim.x + threadIdx.x;
    if (i < Nn) {
        d_beta[i] = 0.0f; d_alpha[i] = 0.0f;
        d_alpha_prev[i] = __int_as_float(0x7fc00000);
        d_beta_prev [i] = __int_as_float(0x7fc00000);
    }
    if (i == 0) g_done = 0;
}

// ---------------- row squared norms: 8-slot FMA chains (FROZEN) -------------
__global__ void rowsq_kernel(const float* __restrict__ X0,
                             const float* __restrict__ X1) {
    int half = (gridDim.x * blockDim.x) >> 1;
    int g = blockIdx.x * blockDim.x + threadIdx.x;
    bool second = g >= half;
    int row = second ? (g - half) : g;
    const float* x = (second ? X1 : X0) + (size_t)row * Dd;
    float s[8];
#pragma unroll
    for (int i = 0; i < 8; i++) s[i] = 0.0f;
    for (int k = 0; k < Dd; k += 8) {
#pragma unroll
        for (int i = 0; i < 8; i++) {
            float v = x[k + i];
            s[i] = __fmaf_rn(v, v, s[i]);
        }
    }
    float w0 = __fadd_rn(s[0], s[4]);
    float w1 = __fadd_rn(s[1], s[5]);
    float w2 = __fadd_rn(s[2], s[6]);
    float w3 = __fadd_rn(s[3], s[7]);
    float r = __fadd_rn(__fadd_rn(w0, w2), __fadd_rn(w1, w3));
    if (second) d_ysq[row] = r; else d_xsq[row] = r;
}

// ---------------- GEMM -> K (FROZEN numerics: sequential-k FMA chain) -------
__global__ void __launch_bounds__(256) gemm_kernel(const float* __restrict__ A,
                                                   const float* __restrict__ B) {
    __shared__ float As[8][128];
    __shared__ float Bs[8][128];
    int bi = blockIdx.y << 7, bj = blockIdx.x << 7;
    int t  = threadIdx.x;
    int tx = t & 15, ty = t >> 4;
    int lrow = t & 127;
    int lk   = (t >> 7) << 2;

    float acc[8][8];
#pragma unroll
    for (int i = 0; i < 8; i++)
#pragma unroll
        for (int j = 0; j < 8; j++) acc[i][j] = 0.f;

    const float* Ag = A + (size_t)(bi + lrow) * Dd + lk;
    const float* Bg = B + (size_t)(bj + lrow) * Dd + lk;

    for (int kt = 0; kt < Dd; kt += 8) {
        float4 av = *(const float4*)(Ag + kt);
        float4 bv = *(const float4*)(Bg + kt);
        __syncthreads();
        As[lk + 0][lrow] = av.x; As[lk + 1][lrow] = av.y;
        As[lk + 2][lrow] = av.z; As[lk + 3][lrow] = av.w;
        Bs[lk + 0][lrow] = bv.x; Bs[lk + 1][lrow] = bv.y;
        Bs[lk + 2][lrow] = bv.z; Bs[lk + 3][lrow] = bv.w;
        __syncthreads();
#pragma unroll
        for (int k = 0; k < 8; k++) {
            float a[8], b[8];
            *(float4*)&a[0] = *(const float4*)&As[k][(ty << 3)];
            *(float4*)&a[4] = *(const float4*)&As[k][(ty << 3) + 4];
            *(float4*)&b[0] = *(const float4*)&Bs[k][(tx << 3)];
            *(float4*)&b[4] = *(const float4*)&Bs[k][(tx << 3) + 4];
#pragma unroll
            for (int i = 0; i < 8; i++)
#pragma unroll
                for (int j = 0; j < 8; j++)
                    acc[i][j] = __fmaf_rn(a[i], b[j], acc[i][j]);
        }
    }

    int row0 = bi + (ty << 3);
    int col0 = bj + (tx << 3);
    float xs[8], ys[8];
#pragma unroll
    for (int i = 0; i < 8; i++) xs[i] = d_xsq[row0 + i];
#pragma unroll
    for (int j = 0; j < 8; j++) ys[j] = d_ysq[col0 + j];
#pragma unroll
    for (int i = 0; i < 8; i++) {
        float o[8];
#pragma unroll
        for (int j = 0; j < 8; j++) {
            float nrm  = __fadd_rn(xs[i], ys[j]);
            float cost = __fmaf_rn(-2.0f, acc[i][j], nrm);
            o[j] = __fdiv_rn(-cost, 0.1f);
        }
        *(float4*)&d_K[(size_t)(row0 + i) * Nn + col0]     = *(float4*)&o[0];
        *(float4*)&d_K[(size_t)(row0 + i) * Nn + col0 + 4] = *(float4*)&o[4];
    }
}

// ---------------- transpose d_K -> d_KT (bitwise copy, one-time) ------------
__global__ void transpose_kernel() {
    __shared__ float tile[32][33];
    int tx = threadIdx.x, ty = threadIdx.y;
    int xi = (blockIdx.x << 5) + tx;
    int yi = (blockIdx.y << 5) + ty;
#pragma unroll
    for (int j = 0; j < 32; j += 8)
        tile[ty + j][tx] = d_K[(size_t)(yi + j) * Nn + xi];
    __syncthreads();
    int xo = (blockIdx.y << 5) + tx;
    int yo = (blockIdx.x << 5) + ty;
#pragma unroll
    for (int j = 0; j < 32; j += 8)
        d_KT[(size_t)(yo + j) * Nn + xo] = tile[tx][ty + j];
}

// =================== LSE PASS: smem stage + warp ballot scan =================
// One block per row. 256 threads load z=fl(K+v) coalesced into smem and
// block-max via shuffle tree. Warp 0 then sweeps 256 conflict-free groups of
// 32 (z[k*32+lane]); ballot vs thr=m-70; for each set bit ascending, lane 0
// accumulates exp_fma(z-m) in EXACT reference order:
//   DIR=0 (alpha): 8-slot (j mod 8) sums + halving combine   [FROZEN]
//   DIR=1 (beta):  strictly sequential ascending i           [FROZEN]
template <int DIR>
__global__ void __launch_bounds__(256) lse_pass_kernel() {
    if (g_done) return;
    __shared__ float z[Nn];      // 32 KB row stage
    __shared__ float wmax[8];
    __shared__ float sslot[8];

    int row = blockIdx.x;
    int t   = threadIdx.x;
    int lane = t & 31, wid = t >> 5;
    const float* __restrict__ Mx  = (DIR == 0) ? d_K  : d_KT;
    const float* __restrict__ vin = (DIR == 0) ? d_beta : d_alpha;
    const float4* src = (const float4*)(Mx + (size_t)row * Nn);
    const float4* vv  = (const float4*)vin;

    // coalesced load + running max (max is order-free => exact)
    float lm = __int_as_float(0xff800000);
#pragma unroll
    for (int k = 0; k < 8; k++) {
        int i4 = k * 256 + t;
        float4 a = src[i4];
        float4 b = vv[i4];
        float4 zv;
        zv.x = __fadd_rn(a.x, b.x); zv.y = __fadd_rn(a.y, b.y);
        zv.z = __fadd_rn(a.z, b.z); zv.w = __fadd_rn(a.w, b.w);
        ((float4*)z)[i4] = zv;
        lm = fmaxf(lm, fmaxf(fmaxf(zv.x, zv.y), fmaxf(zv.z, zv.w)));
    }
#pragma unroll
    for (int off = 16; off; off >>= 1)
        lm = fmaxf(lm, __shfl_down_sync(0xffffffffu, lm, off));
    if (lane == 0) wmax[wid] = lm;
    __syncthreads();

    if (wid == 0) {
        float m = (lane < 8) ? wmax[lane] : __int_as_float(0xff800000);
#pragma unroll
        for (int off = 4; off; off >>= 1)
            m = fmaxf(m, __shfl_down_sync(0xffffffffu, m, off));
        m = __shfl_sync(0xffffffffu, m, 0);
        float thr = m - 70.0f;

        if (lane == 0) {
#pragma unroll
            for (int i = 0; i < 8; i++) sslot[i] = 0.0f;
        }
        float acc = 0.0f;   // DIR=1 accumulator (lane 0)

        for (int k = 0; k < 256; k++) {
            float v = z[k * 32 + lane];            // conflict-free
            unsigned mask = __ballot_sync(0xffffffffu, v >= thr);
            while (mask) {                          // uniform loop (mask uniform)
                int b = __ffs(mask) - 1;
                float val = __shfl_sync(0xffffffffu, v, b);
                if (lane == 0) {
                    float e = exp_fma(__fadd_rn(val, -m));
                    if (DIR == 0) {
                        int slot = (k * 32 + b) & 7;
                        sslot[slot] = __fadd_rn(sslot[slot], e);
                    } else {
                        acc = __fadd_rn(acc, e);
                    }
                }
                mask &= mask - 1;
            }
        }

        if (lane == 0) {
            float S;
            if (DIR == 0) {
                float w0 = __fadd_rn(sslot[0], sslot[4]);
                float w1 = __fadd_rn(sslot[1], sslot[5]);
                float w2 = __fadd_rn(sslot[2], sslot[6]);
                float w3 = __fadd_rn(sslot[3], sslot[7]);
                S = __fadd_rn(__fadd_rn(w0, w2), __fadd_rn(w1, w3));
            } else {
                S = acc;
            }
            float res = -__fadd_rn(log_fma(S), m);
            if (DIR == 0) d_alpha[row] = res; else d_beta[row] = res;
        }
    }
}

// ---------------- convergence: exact fp32 fixed point -----------------------
__global__ void __launch_bounds__(1024) conv_kernel() {
    if (g_done) return;
    __shared__ int diff;
    if (threadIdx.x == 0) diff = 0;
    __syncthreads();
    int ld = 0;
    for (int i = threadIdx.x; i < Nn; i += 1024) {
        ld |= (__float_as_int(d_alpha[i]) != __float_as_int(d_alpha_prev[i]));
        ld |= (__float_as_int(d_beta[i])  != __float_as_int(d_beta_prev[i]));
        d_alpha_prev[i] = d_alpha[i];
        d_beta_prev[i]  = d_beta[i];
    }
    if (ld) atomicOr(&diff, 1);
    __syncthreads();
    if (threadIdx.x == 0 && diff == 0) g_done = 1;
}

// ---------------- argmax over P = exp_fma(fl(fl(K+alpha)+beta)) (FROZEN) ----
__global__ void __launch_bounds__(256) argmax_kernel() {
    int rowbase = blockIdx.x << 3;
    int t = threadIdx.x;
    float a[8];
#pragma unroll
    for (int r = 0; r < 8; r++) a[r] = d_alpha[rowbase + r];

    float bv[8]; int bi_[8];
#pragma unroll
    for (int r = 0; r < 8; r++) { bv[r] = -1.0f; bi_[r] = Nn; }

    for (int c = t << 2; c < Nn; c += 1024) {
        float4 betav = *(const float4*)(d_beta + c);
#pragma unroll
        for (int r = 0; r < 8; r++) {
            float4 v = *(const float4*)(d_K + (size_t)(rowbase + r) * Nn + c);
            float w;
            w = exp_fma(__fadd_rn(__fadd_rn(v.x, a[r]), betav.x)); if (w > bv[r]) { bv[r] = w; bi_[r] = c; }
            w = exp_fma(__fadd_rn(__fadd_rn(v.y, a[r]), betav.y)); if (w > bv[r]) { bv[r] = w; bi_[r] = c + 1; }
            w = exp_fma(__fadd_rn(__fadd_rn(v.z, a[r]), betav.z)); if (w > bv[r]) { bv[r] = w; bi_[r] = c + 2; }
            w = exp_fma(__fadd_rn(__fadd_rn(v.w, a[r]), betav.w)); if (w > bv[r]) { bv[r] = w; bi_[r] = c + 3; }
        }
    }
#pragma unroll
    for (int r = 0; r < 8; r++) {
#pragma unroll
        for (int off = 16; off; off >>= 1) {
            float ov = __shfl_down_sync(0xffffffffu, bv[r], off);
            int   oi = __shfl_down_sync(0xffffffffu, bi_[r], off);
            if (ov > bv[r] || (ov == bv[r] && oi < bi_[r])) { bv[r] = ov; bi_[r] = oi; }
        }
    }
    __shared__ float svv[8][8];
    __shared__ int   sii[8][8];
    int wid = t >> 5, lane = t & 31;
    if (lane == 0) {
#pragma unroll
        for (int r = 0; r < 8; r++) { svv[r][wid] = bv[r]; sii[r][wid] = bi_[r]; }
    }
    __syncthreads();
    if (t < 8) {
        float V = -1.0f; int I = Nn;
#pragma unroll
        for (int w = 0; w < 8; w++) {
            float ov = svv[t][w]; int oi = sii[t][w];
            if (ov > V || (ov == V && oi < I)) { V = ov; I = oi; }
        }
        d_idx[rowbase + t] = I;
    }
}

// ---------------- out = concat(x0, x1[idx]) ----------------
__global__ void output_kernel(const float* __restrict__ x0,
                              const float* __restrict__ x1,
                              float* __restrict__ out) {
    int row = blockIdx.x;
    int t   = threadIdx.x;
    const float4* s0 = (const float4*)(x0 + (size_t)row * Dd);
    ((float4*)(out + (size_t)row * Dd))[t] = s0[t];
    int j = d_idx[row];
    const float4* s1 = (const float4*)(x1 + (size_t)j * Dd);
    ((float4*)(out + (size_t)Nn * Dd + (size_t)row * Dd))[t] = s1[t];
}

// ---------------- launch ----------------
extern "C" void kernel_launch(void* const* d_in, const int* in_sizes, int n_in,
                              void* d_out, int out_size) {
    const float* x0 = (const float*)d_in[0];
    const float* x1 = (const float*)d_in[1];
    float* out = (float*)d_out;

    init_kernel<<<8, 1024>>>();
    rowsq_kernel<<<2 * (Nn / 256), 256>>>(x0, x1);

    dim3 gg(Nn / 128, Nn / 128);
    gemm_kernel<<<gg, 256>>>(x0, x1);

    dim3 tg(Nn / 32, Nn / 32), tb(32, 8);
    transpose_kernel<<<tg, tb>>>();

    for (int it = 0; it < 100; it++) {
        lse_pass_kernel<0><<<Nn, 256>>>();
        lse_pass_kernel<1><<<Nn, 256>>>();
        conv_kernel<<<1, 1024>>>();
    }

    argmax_kernel<<<Nn / 8, 256>>>();
    output_kernel<<<Nn, 128>>>(x0, x1, out);
}

// round 11
// speedup vs baseline: 4.4793x; 1.8256x over previous
#include <cuda_runtime.h>
#include <math.h>

#define Nn 8192
#define Dd 512
#define SEGCAP 128   // per-segment candidate cap (exact in-order fallback if hit)

// ---------------- static device scratch (symbol-access only) ----------------
static __device__ float d_K [(size_t)Nn * Nn];   // log_K on reference fp32 grid
static __device__ float d_KT[(size_t)Nn * Nn];   // transpose (same bits)
static __device__ float d_alpha[Nn];
static __device__ float d_beta [Nn];
static __device__ float d_alpha_prev[Nn];
static __device__ float d_beta_prev [Nn];
static __device__ float d_xsq[Nn];
static __device__ float d_ysq[Nn];
static __device__ int   d_idx[Nn];
static __device__ int   g_done;

// ---- FROZEN NUMERICS (Round 8 pass): XLA-CPU cephes exp, FMA-contracted ----
static __device__ __forceinline__ float exp_fma(float x) {
    x = fminf(x, 88.3762626647950f);
    x = fmaxf(x, -88.3762626647949f);
    float fx = floorf(__fmaf_rn(x, 1.44269504088896341f, 0.5f));
    float r  = __fmaf_rn(fx, -0.693359375f, x);
    r        = __fmaf_rn(fx,  2.12194440e-4f, r);
    float z  = __fmul_rn(r, r);
    float y  = __fmaf_rn(1.9875691500e-4f, r, 1.3981999507e-3f);
    y = __fmaf_rn(y, r, 8.3334519073e-3f);
    y = __fmaf_rn(y, r, 4.1665795894e-2f);
    y = __fmaf_rn(y, r, 1.6666665459e-1f);
    y = __fmaf_rn(y, r, 5.0000001201e-1f);
    y = __fmaf_rn(y, z, r);
    y = __fadd_rn(1.0f, y);
    int n = (int)fx;
    float s = __int_as_float((unsigned)(n + 127) << 23);
    return __fmul_rn(y, s);
}

// ---- FROZEN: XLA-CPU cephes log, FMA-contracted (S >= 1 here) ----
static __device__ __forceinline__ float log_fma(float x) {
    int bits = __float_as_int(x);
    int e = (bits >> 23) - 126;
    float mant = __int_as_float((bits & 0x007fffff) | 0x3f000000);  // [0.5,1)
    if (mant < 0.707106781186547524f) {
        e -= 1;
        mant = __fadd_rn(__fadd_rn(mant, mant), -1.0f);
    } else {
        mant = __fadd_rn(mant, -1.0f);
    }
    float z = __fmul_rn(mant, mant);
    float y = 7.0376836292e-2f;
    y = __fmaf_rn(y, mant, -1.1514610310e-1f);
    y = __fmaf_rn(y, mant,  1.1676998740e-1f);
    y = __fmaf_rn(y, mant, -1.2420140846e-1f);
    y = __fmaf_rn(y, mant,  1.4249322787e-1f);
    y = __fmaf_rn(y, mant, -1.6668057665e-1f);
    y = __fmaf_rn(y, mant,  2.0000714765e-1f);
    y = __fmaf_rn(y, mant, -2.4999993993e-1f);
    y = __fmaf_rn(y, mant,  3.3333331174e-1f);
    y = __fmul_rn(__fmul_rn(y, mant), z);
    float fe = (float)e;
    y = __fmaf_rn(fe, -2.12194440e-4f, y);
    y = __fmaf_rn(-0.5f, z, y);
    float res = __fadd_rn(mant, y);
    res = __fmaf_rn(fe, 0.693359375f, res);
    return res;
}

// ---------------- init ----------------
__global__ void init_kernel() {
    int i = blockIdx.x * blockDim.x + threadIdx.x;
    if (i < Nn) {
        d_beta[i] = 0.0f; d_alpha[i] = 0.0f;
        d_alpha_prev[i] = __int_as_float(0x7fc00000);
        d_beta_prev [i] = __int_as_float(0x7fc00000);
    }
    if (i == 0) g_done = 0;
}

// ---------------- row squared norms: 8-slot FMA chains (FROZEN) -------------
__global__ void rowsq_kernel(const float* __restrict__ X0,
                             const float* __restrict__ X1) {
    int half = (gridDim.x * blockDim.x) >> 1;
    int g = blockIdx.x * blockDim.x + threadIdx.x;
    bool second = g >= half;
    int row = second ? (g - half) : g;
    const float* x = (second ? X1 : X0) + (size_t)row * Dd;
    float s[8];
#pragma unroll
    for (int i = 0; i < 8; i++) s[i] = 0.0f;
    for (int k = 0; k < Dd; k += 8) {
#pragma unroll
        for (int i = 0; i < 8; i++) {
            float v = x[k + i];
            s[i] = __fmaf_rn(v, v, s[i]);
        }
    }
    float w0 = __fadd_rn(s[0], s[4]);
    float w1 = __fadd_rn(s[1], s[5]);
    float w2 = __fadd_rn(s[2], s[6]);
    float w3 = __fadd_rn(s[3], s[7]);
    float r = __fadd_rn(__fadd_rn(w0, w2), __fadd_rn(w1, w3));
    if (second) d_ysq[row] = r; else d_xsq[row] = r;
}

// ---------------- GEMM -> K (FROZEN numerics: sequential-k FMA chain) -------
__global__ void __launch_bounds__(256) gemm_kernel(const float* __restrict__ A,
                                                   const float* __restrict__ B) {
    __shared__ float As[8][128];
    __shared__ float Bs[8][128];
    int bi = blockIdx.y << 7, bj = blockIdx.x << 7;
    int t  = threadIdx.x;
    int tx = t & 15, ty = t >> 4;
    int lrow = t & 127;
    int lk   = (t >> 7) << 2;

    float acc[8][8];
#pragma unroll
    for (int i = 0; i < 8; i++)
#pragma unroll
        for (int j = 0; j < 8; j++) acc[i][j] = 0.f;

    const float* Ag = A + (size_t)(bi + lrow) * Dd + lk;
    const float* Bg = B + (size_t)(bj + lrow) * Dd + lk;

    for (int kt = 0; kt < Dd; kt += 8) {
        float4 av = *(const float4*)(Ag + kt);
        float4 bv = *(const float4*)(Bg + kt);
        __syncthreads();
        As[lk + 0][lrow] = av.x; As[lk + 1][lrow] = av.y;
        As[lk + 2][lrow] = av.z; As[lk + 3][lrow] = av.w;
        Bs[lk + 0][lrow] = bv.x; Bs[lk + 1][lrow] = bv.y;
        Bs[lk + 2][lrow] = bv.z; Bs[lk + 3][lrow] = bv.w;
        __syncthreads();
#pragma unroll
        for (int k = 0; k < 8; k++) {
            float a[8], b[8];
            *(float4*)&a[0] = *(const float4*)&As[k][(ty << 3)];
            *(float4*)&a[4] = *(const float4*)&As[k][(ty << 3) + 4];
            *(float4*)&b[0] = *(const float4*)&Bs[k][(tx << 3)];
            *(float4*)&b[4] = *(const float4*)&Bs[k][(tx << 3) + 4];
#pragma unroll
            for (int i = 0; i < 8; i++)
#pragma unroll
                for (int j = 0; j < 8; j++)
                    acc[i][j] = __fmaf_rn(a[i], b[j], acc[i][j]);
        }
    }

    int row0 = bi + (ty << 3);
    int col0 = bj + (tx << 3);
    float xs[8], ys[8];
#pragma unroll
    for (int i = 0; i < 8; i++) xs[i] = d_xsq[row0 + i];
#pragma unroll
    for (int j = 0; j < 8; j++) ys[j] = d_ysq[col0 + j];
#pragma unroll
    for (int i = 0; i < 8; i++) {
        float o[8];
#pragma unroll
        for (int j = 0; j < 8; j++) {
            float nrm  = __fadd_rn(xs[i], ys[j]);
            float cost = __fmaf_rn(-2.0f, acc[i][j], nrm);
            o[j] = __fdiv_rn(-cost, 0.1f);
        }
        *(float4*)&d_K[(size_t)(row0 + i) * Nn + col0]     = *(float4*)&o[0];
        *(float4*)&d_K[(size_t)(row0 + i) * Nn + col0 + 4] = *(float4*)&o[4];
    }
}

// ---------------- transpose d_K -> d_KT (bitwise copy, one-time) ------------
__global__ void transpose_kernel() {
    __shared__ float tile[32][33];
    int tx = threadIdx.x, ty = threadIdx.y;
    int xi = (blockIdx.x << 5) + tx;
    int yi = (blockIdx.y << 5) + ty;
#pragma unroll
    for (int j = 0; j < 32; j += 8)
        tile[ty + j][tx] = d_K[(size_t)(yi + j) * Nn + xi];
    __syncthreads();
    int xo = (blockIdx.y << 5) + tx;
    int yo = (blockIdx.x << 5) + ty;
#pragma unroll
    for (int j = 0; j < 32; j += 8)
        d_KT[(size_t)(yo + j) * Nn + xo] = tile[tx][ty + j];
}

// =================== LSE PASS: smem stage + 8-warp segmented ballot scan ====
// One block per row. 256 threads load z=fl(K+v) into smem (+block max).
// Warp w scans segment [w*1024,(w+1)*1024) in 32 conflict-free ballot groups;
// lane 0 appends segment-local candidate indices (ascending by construction).
// Thread 0 then walks segments 0..7 => globally ascending candidate order and
// accumulates exp_fma(z-m) with the FROZEN order:
//   DIR=0 (alpha): 8-slot (j mod 8) sums + halving combine
//   DIR=1 (beta):  strictly sequential
template <int DIR>
__global__ void __launch_bounds__(256) lse_pass_kernel() {
    if (g_done) return;
    __shared__ float z[Nn];      // 32 KB row stage
    __shared__ float wmax[8];
    __shared__ float bmax_s;
    __shared__ int   seg_cnt[8];
    __shared__ short seg_list[8][SEGCAP];

    int row = blockIdx.x;
    int t   = threadIdx.x;
    int lane = t & 31, wid = t >> 5;
    const float* __restrict__ Mx  = (DIR == 0) ? d_K  : d_KT;
    const float* __restrict__ vin = (DIR == 0) ? d_beta : d_alpha;
    const float4* src = (const float4*)(Mx + (size_t)row * Nn);
    const float4* vv  = (const float4*)vin;

    // coalesced load + running max (max is order-free => exact)
    float lm = __int_as_float(0xff800000);
#pragma unroll
    for (int k = 0; k < 8; k++) {
        int i4 = k * 256 + t;
        float4 a = src[i4];
        float4 b = vv[i4];
        float4 zv;
        zv.x = __fadd_rn(a.x, b.x); zv.y = __fadd_rn(a.y, b.y);
        zv.z = __fadd_rn(a.z, b.z); zv.w = __fadd_rn(a.w, b.w);
        ((float4*)z)[i4] = zv;
        lm = fmaxf(lm, fmaxf(fmaxf(zv.x, zv.y), fmaxf(zv.z, zv.w)));
    }
#pragma unroll
    for (int off = 16; off; off >>= 1)
        lm = fmaxf(lm, __shfl_down_sync(0xffffffffu, lm, off));
    if (lane == 0) { wmax[wid] = lm; seg_cnt[wid] = 0; }
    __syncthreads();

    if (wid == 0) {
        float m = (lane < 8) ? wmax[lane] : __int_as_float(0xff800000);
#pragma unroll
        for (int off = 4; off; off >>= 1)
            m = fmaxf(m, __shfl_down_sync(0xffffffffu, m, off));
        if (lane == 0) bmax_s = m;
    }
    __syncthreads();
    float m   = bmax_s;
    float thr = m - 70.0f;

    // segmented ballot scan: warp wid, groups ascending, candidates ascending
    {
        int base = wid * 1024;
        int cnt = 0;
#pragma unroll 4
        for (int k = 0; k < 32; k++) {
            float v = z[base + k * 32 + lane];     // conflict-free
            unsigned mask = __ballot_sync(0xffffffffu, v >= thr);
            if (lane == 0) {
                while (mask) {
                    int b = __ffs(mask) - 1;
                    if (cnt < SEGCAP) seg_list[wid][cnt] = (short)(k * 32 + b);
                    cnt++;
                    mask &= mask - 1;
                }
            }
        }
        if (lane == 0) seg_cnt[wid] = cnt;
    }
    __syncthreads();

    if (t == 0) {
        bool ok = true;
#pragma unroll
        for (int w = 0; w < 8; w++) ok &= (seg_cnt[w] <= SEGCAP);

        float S;
        if (ok) {
            if (DIR == 0) {
                float s[8];
#pragma unroll
                for (int i = 0; i < 8; i++) s[i] = 0.0f;
                for (int w = 0; w < 8; w++) {
                    int base = w * 1024, cnt = seg_cnt[w];
                    for (int p = 0; p < cnt; p++) {
                        int idx = base + seg_list[w][p];
                        s[idx & 7] = __fadd_rn(s[idx & 7], exp_fma(__fadd_rn(z[idx], -m)));
                    }
                }
                float w0 = __fadd_rn(s[0], s[4]);
                float w1 = __fadd_rn(s[1], s[5]);
                float w2 = __fadd_rn(s[2], s[6]);
                float w3 = __fadd_rn(s[3], s[7]);
                S = __fadd_rn(__fadd_rn(w0, w2), __fadd_rn(w1, w3));
            } else {
                float acc = 0.0f;
                for (int w = 0; w < 8; w++) {
                    int base = w * 1024, cnt = seg_cnt[w];
                    for (int p = 0; p < cnt; p++) {
                        int idx = base + seg_list[w][p];
                        acc = __fadd_rn(acc, exp_fma(__fadd_rn(z[idx], -m)));
                    }
                }
                S = acc;
            }
        } else {
            // exact in-order fallback over staged row (never touches DRAM)
            if (DIR == 0) {
                float s[8];
#pragma unroll
                for (int i = 0; i < 8; i++) s[i] = 0.0f;
                for (int q = 0; q < Nn; q++)
                    if (z[q] >= thr)
                        s[q & 7] = __fadd_rn(s[q & 7], exp_fma(__fadd_rn(z[q], -m)));
                float w0 = __fadd_rn(s[0], s[4]);
                float w1 = __fadd_rn(s[1], s[5]);
                float w2 = __fadd_rn(s[2], s[6]);
                float w3 = __fadd_rn(s[3], s[7]);
                S = __fadd_rn(__fadd_rn(w0, w2), __fadd_rn(w1, w3));
            } else {
                float acc = 0.0f;
                for (int q = 0; q < Nn; q++)
                    if (z[q] >= thr)
                        acc = __fadd_rn(acc, exp_fma(__fadd_rn(z[q], -m)));
                S = acc;
            }
        }
        float res = -__fadd_rn(log_fma(S), m);
        if (DIR == 0) d_alpha[row] = res; else d_beta[row] = res;
    }
}

// ---------------- convergence: exact fp32 fixed point -----------------------
__global__ void __launch_bounds__(1024) conv_kernel() {
    if (g_done) return;
    __shared__ int diff;
    if (threadIdx.x == 0) diff = 0;
    __syncthreads();
    int ld = 0;
    for (int i = threadIdx.x; i < Nn; i += 1024) {
        ld |= (__float_as_int(d_alpha[i]) != __float_as_int(d_alpha_prev[i]));
        ld |= (__float_as_int(d_beta[i])  != __float_as_int(d_beta_prev[i]));
        d_alpha_prev[i] = d_alpha[i];
        d_beta_prev[i]  = d_beta[i];
    }
    if (ld) atomicOr(&diff, 1);
    __syncthreads();
    if (threadIdx.x == 0 && diff == 0) g_done = 1;
}

// ---------------- argmax over P = exp_fma(fl(fl(K+alpha)+beta)) (FROZEN) ----
__global__ void __launch_bounds__(256) argmax_kernel() {
    int rowbase = blockIdx.x << 3;
    int t = threadIdx.x;
    float a[8];
#pragma unroll
    for (int r = 0; r < 8; r++) a[r] = d_alpha[rowbase + r];

    float bv[8]; int bi_[8];
#pragma unroll
    for (int r = 0; r < 8; r++) { bv[r] = -1.0f; bi_[r] = Nn; }

    for (int c = t << 2; c < Nn; c += 1024) {
        float4 betav = *(const float4*)(d_beta + c);
#pragma unroll
        for (int r = 0; r < 8; r++) {
            float4 v = *(const float4*)(d_K + (size_t)(rowbase + r) * Nn + c);
            float w;
            w = exp_fma(__fadd_rn(__fadd_rn(v.x, a[r]), betav.x)); if (w > bv[r]) { bv[r] = w; bi_[r] = c; }
            w = exp_fma(__fadd_rn(__fadd_rn(v.y, a[r]), betav.y)); if (w > bv[r]) { bv[r] = w; bi_[r] = c + 1; }
            w = exp_fma(__fadd_rn(__fadd_rn(v.z, a[r]), betav.z)); if (w > bv[r]) { bv[r] = w; bi_[r] = c + 2; }
            w = exp_fma(__fadd_rn(__fadd_rn(v.w, a[r]), betav.w)); if (w > bv[r]) { bv[r] = w; bi_[r] = c + 3; }
        }
    }
#pragma unroll
    for (int r = 0; r < 8; r++) {
#pragma unroll
        for (int off = 16; off; off >>= 1) {
            float ov = __shfl_down_sync(0xffffffffu, bv[r], off);
            int   oi = __shfl_down_sync(0xffffffffu, bi_[r], off);
            if (ov > bv[r] || (ov == bv[r] && oi < bi_[r])) { bv[r] = ov; bi_[r] = oi; }
        }
    }
    __shared__ float svv[8][8];
    __shared__ int   sii[8][8];
    int wid = t >> 5, lane = t & 31;
    if (lane == 0) {
#pragma unroll
        for (int r = 0; r < 8; r++) { svv[r][wid] = bv[r]; sii[r][wid] = bi_[r]; }
    }
    __syncthreads();
    if (t < 8) {
        float V = -1.0f; int I = Nn;
#pragma unroll
        for (int w = 0; w < 8; w++) {
            float ov = svv[t][w]; int oi = sii[t][w];
            if (ov > V || (ov == V && oi < I)) { V = ov; I = oi; }
        }
        d_idx[rowbase + t] = I;
    }
}

// ---------------- out = concat(x0, x1[idx]) ----------------
__global__ void output_kernel(const float* __restrict__ x0,
                              const float* __restrict__ x1,
                              float* __restrict__ out) {
    int row = blockIdx.x;
    int t   = threadIdx.x;
    const float4* s0 = (const float4*)(x0 + (size_t)row * Dd);
    ((float4*)(out + (size_t)row * Dd))[t] = s0[t];
    int j = d_idx[row];
    const float4* s1 = (const float4*)(x1 + (size_t)j * Dd);
    ((float4*)(out + (size_t)Nn * Dd + (size_t)row * Dd))[t] = s1[t];
}

// ---------------- launch ----------------
extern "C" void kernel_launch(void* const* d_in, const int* in_sizes, int n_in,
                              void* d_out, int out_size) {
    const float* x0 = (const float*)d_in[0];
    const float* x1 = (const float*)d_in[1];
    float* out = (float*)d_out;

    init_kernel<<<8, 1024>>>();
    rowsq_kernel<<<2 * (Nn / 256), 256>>>(x0, x1);

    dim3 gg(Nn / 128, Nn / 128);
    gemm_kernel<<<gg, 256>>>(x0, x1);

    dim3 tg(Nn / 32, Nn / 32), tb(32, 8);
    transpose_kernel<<<tg, tb>>>();

    for (int it = 0; it < 100; it++) {
        lse_pass_kernel<0><<<Nn, 256>>>();
        lse_pass_kernel<1><<<Nn, 256>>>();
        if (it & 1) conv_kernel<<<1, 1024>>>();
    }

    argmax_kernel<<<Nn / 8, 256>>>();
    output_kernel<<<Nn, 128>>>(x0, x1, out);
}